// round 16
// baseline (speedup 1.0000x reference)
#include <cuda_runtime.h>
#include <cuda_fp16.h>
#include <cstdint>

// ----------------------------------------------------------------------------
// B=128, T=32, F=2048, H=1024, L=20, WV=300; TF gate order i,j,f,o; FORGET_BIAS=1
// ----------------------------------------------------------------------------
#define B_   128
#define T_   32
#define F_   2048
#define H_   1024
#define L_   20
#define WV_  300
#define G4H  4096
#define NBLK 128
#define STG_WORDS 6144       // mm0 stage: A 128x16 (2048) + B 16x256 (4096)
#define SMEM_BIG  (3 * STG_WORDS * 4)
// persist: 3 stages x (A 128x32 + B 32x128) = 3 x 8192 floats = 96KB
#define PST_STG   8192
#define SMEM_PST  (3 * PST_STG * 4)
#define PST_NK    8          // 8 x BK32 = 256 k per block
#define ZPSZ      ((size_t)128 * 128 * 128)

// ---------------- device scratch ----------------
__device__ float g_xg_enc[(size_t)4096 * 4096];   // [t*128+b][4H]
__device__ float g_xg_dec[(size_t)2560 * 4096];   // [l*128+b][4H]
__device__ float g_zp[2 * ZPSZ];                  // [t&1][bid][batch 128][col 128]
__device__ float g_hbuf[3][B_ * H_];              // triple-buffered h (tf32-rounded)
__device__ float g_hs[(size_t)L_ * B_ * H_];      // decoder outputs
__device__ float g_whE[(size_t)H_ * G4H];         // tf32-rounded Wh (encoder)
__device__ float g_whD[(size_t)H_ * G4H];         // tf32-rounded Wh (decoder)
__device__ float g_wx[(size_t)F_ * G4H];          // tf32-rounded Wx (encoder, [k][n])
__device__ float g_frames_tf[(size_t)4096 * F_];  // [m=t*128+b][k] tf32 frames
__device__ unsigned g_flagZ[NBLK * 8];            // zp-ready (value = t+1)
__device__ unsigned g_flagH[NBLK * 8];            // gates-done (value = t+1)

// ---------------- helpers ----------------
__device__ __forceinline__ float f2tf(float x) {
    unsigned u;
    asm("cvt.rna.tf32.f32 %0, %1;" : "=r"(u) : "f"(x));
    return __uint_as_float(u);
}
__device__ __forceinline__ float4 tf4(float4 v) {
    return make_float4(f2tf(v.x), f2tf(v.y), f2tf(v.z), f2tf(v.w));
}
__device__ __forceinline__ void mma8(float* c, const float* a, const float* b) {
    asm volatile(
        "mma.sync.aligned.m16n8k8.row.col.f32.tf32.tf32.f32 "
        "{%0,%1,%2,%3},{%4,%5,%6,%7},{%8,%9},{%0,%1,%2,%3};"
        : "+f"(c[0]), "+f"(c[1]), "+f"(c[2]), "+f"(c[3])
        : "r"(__float_as_uint(a[0])), "r"(__float_as_uint(a[1])),
          "r"(__float_as_uint(a[2])), "r"(__float_as_uint(a[3])),
          "r"(__float_as_uint(b[0])), "r"(__float_as_uint(b[1])));
}
__device__ __forceinline__ void mma16h(float* c, const uint32_t* a, const uint32_t* b) {
    asm volatile(
        "mma.sync.aligned.m16n8k16.row.col.f32.f16.f16.f32 "
        "{%0,%1,%2,%3},{%4,%5,%6,%7},{%8,%9},{%0,%1,%2,%3};"
        : "+f"(c[0]), "+f"(c[1]), "+f"(c[2]), "+f"(c[3])
        : "r"(a[0]), "r"(a[1]), "r"(a[2]), "r"(a[3]), "r"(b[0]), "r"(b[1]));
}
__device__ __forceinline__ uint32_t pack_h2(float lo, float hi) {
    __half2 h = __floats2half2_rn(lo, hi);   // x=lo (low 16b), y=hi
    return *(uint32_t*)&h;
}
__device__ __forceinline__ float2 add2(float2 a, float2 b) {
    a.x += b.x; a.y += b.y; return a;
}
__device__ __forceinline__ float sigf(float x) { return 1.f / (1.f + __expf(-x)); }

__device__ __forceinline__ uint32_t smem_u32(const void* p) {
    return (uint32_t)__cvta_generic_to_shared(p);
}
__device__ __forceinline__ void cpa16(uint32_t dst, const void* src) {
    asm volatile("cp.async.cg.shared.global [%0], [%1], 16;" :: "r"(dst), "l"(src));
}
#define CP_COMMIT() asm volatile("cp.async.commit_group;")
#define CP_WAIT1()  asm volatile("cp.async.wait_group 1;")

// ============================================================================
// mm0_big: enc XG GEMM, tile 128x256, BK=16, fp32 smem (R15-verified layout),
// fp16 m16n8k16 compute (fragments packed from floats at load time).
// A smem: col c of row m stored at c ^ (((m>>1)&3)<<2).
// B smem: col n of row k stored at n ^ ((k&3)<<3), stride 256.
// ============================================================================
struct CoreIds {
    int lane, wid, wm, wn, gid, tig, swzA;
    int ar, akq, a_dst;
    int bk, bn, b_dst;
};
__device__ __forceinline__ CoreIds core_ids(int tid) {
    CoreIds s;
    s.lane = tid & 31; s.wid = tid >> 5;
    s.wm = s.wid >> 2; s.wn = s.wid & 3;
    s.gid = s.lane >> 2; s.tig = s.lane & 3;
    s.swzA = ((s.gid >> 1) & 3) << 2;
    s.ar = tid >> 2; s.akq = (tid & 3) << 2;
    s.a_dst = s.ar * 16 + (s.akq ^ (((s.ar >> 1) & 3) << 2));
    s.bk = tid >> 5; s.bn = (tid & 31) * 8;
    s.b_dst = 2048 + s.bk * 256 + (s.bn ^ ((s.bk & 3) << 3));
    return s;
}

// f16 compute over one BK16 tile (mm0 shape: 8 nf, B stride 256)
__device__ __forceinline__ void core_h16_mm0(
    const float* __restrict__ a_s, const float* __restrict__ b_s,
    const CoreIds& s, float acc[2][8][4])
{
    uint32_t af[2][4], bf[8][2];
    const int kA  = (2 * s.tig) ^ s.swzA;        // pair (k, k+1) contiguous
    const int kA8 = (2 * s.tig + 8) ^ s.swzA;
#pragma unroll
    for (int mf = 0; mf < 2; mf++) {
        const int m0 = s.wm * 32 + mf * 16 + s.gid;
        float2 p;
        p = *(const float2*)&a_s[m0 * 16 + kA];        af[mf][0] = pack_h2(p.x, p.y);
        p = *(const float2*)&a_s[(m0 + 8) * 16 + kA];  af[mf][1] = pack_h2(p.x, p.y);
        p = *(const float2*)&a_s[m0 * 16 + kA8];       af[mf][2] = pack_h2(p.x, p.y);
        p = *(const float2*)&a_s[(m0 + 8) * 16 + kA8]; af[mf][3] = pack_h2(p.x, p.y);
    }
    const int r0 = 2 * s.tig, r1 = r0 + 1, r2 = r0 + 8, r3 = r0 + 9;
#pragma unroll
    for (int nf = 0; nf < 8; nf++) {
        const int n = s.wn * 64 + nf * 8 + s.gid;
        bf[nf][0] = pack_h2(b_s[r0 * 256 + (n ^ ((r0 & 3) << 3))],
                            b_s[r1 * 256 + (n ^ ((r1 & 3) << 3))]);
        bf[nf][1] = pack_h2(b_s[r2 * 256 + (n ^ ((r2 & 3) << 3))],
                            b_s[r3 * 256 + (n ^ ((r3 & 3) << 3))]);
    }
#pragma unroll
    for (int mf = 0; mf < 2; mf++)
#pragma unroll
        for (int nf = 0; nf < 8; nf++) mma16h(acc[mf][nf], af[mf], bf[nf]);
}

__global__ void __launch_bounds__(512)
mm0_big(const float* __restrict__ bias)
{
    extern __shared__ float dsm[];
    const int tid = threadIdx.x;
    const CoreIds s = core_ids(tid);
    const uint32_t smb = smem_u32(dsm);
    const int ntile = blockIdx.x, mtile = blockIdx.y;

    const float* arow = g_frames_tf + (size_t)(mtile * 128 + s.ar) * F_;
    const float* bsrc = g_wx + ntile * 256 + s.bn;

    float acc[2][8][4] = {};
    const int NK = F_ / 16;

    auto issue = [&](int st) {
        const uint32_t sb = smb + (uint32_t)((st % 3) * STG_WORDS) * 4;
        const int kb = st * 16;
        cpa16(sb + s.a_dst * 4, arow + kb + s.akq);
        const float* bp = bsrc + (size_t)(kb + s.bk) * G4H;
        cpa16(sb + s.b_dst * 4, bp);
        cpa16(sb + (s.b_dst + 4) * 4, bp + 4);
    };

    issue(0); CP_COMMIT();
    issue(1); CP_COMMIT();

    for (int kt = 0; kt < NK; ++kt) {
        CP_WAIT1();
        __syncthreads();
        if (kt + 2 < NK) issue(kt + 2);
        CP_COMMIT();
        const float* a_s = dsm + (kt % 3) * STG_WORDS;
        core_h16_mm0(a_s, a_s + 2048, s, acc);
    }

#pragma unroll
    for (int mf = 0; mf < 2; mf++)
#pragma unroll
        for (int nf = 0; nf < 8; nf++) {
            const int col = ntile * 256 + s.wn * 64 + nf * 8 + 2 * s.tig;
            const float2 bb = *(const float2*)(bias + col);
#pragma unroll
            for (int r = 0; r < 2; r++) {
                const int row = mtile * 128 + s.wm * 32 + mf * 16 + s.gid + r * 8;
                *(float2*)&g_xg_enc[(size_t)row * G4H + col] =
                    make_float2(acc[mf][nf][2 * r] + bb.x,
                                acc[mf][nf][2 * r + 1] + bb.y);
            }
        }
}

// ============================================================================
// Persistent recurrence: R15 pipeline/sync (verified) with fp16 m16n8k16
// compute over the same fp32 smem tiles. B stride 128, storage xor
// n ^ ((k&3)<<3); A as in mm0.
// ============================================================================
__global__ void __launch_bounds__(512)
lstm_persist()
{
    extern __shared__ float dsm[];   // 3 stages x [A0 2048|A1 2048|B0 2048|B1 2048]
    const int tid = threadIdx.x, bid = blockIdx.x;
    const int g = bid >> 2, ks = bid & 3;
    const int hc0 = g * 32;
    const int k0 = ks * 256;

    const int lane = tid & 31, wid = tid >> 5;
    const int wm = wid >> 2, wn = wid & 3;
    const int gid = lane >> 2, tig = lane & 3;
    const int swzA = ((gid >> 1) & 3) << 2;

    const int ar = tid >> 2, akq = (tid & 3) * 4;
    const int a_dst = ar * 16 + (akq ^ (((ar >> 1) & 3) << 2));
    const int bk = tid >> 5, bseg = (tid & 31) >> 3, bnn = (tid & 7) * 4;
    const int b_dst = bk * 128 + ((bseg * 32 + bnn) ^ ((bk & 3) * 8));
    const size_t b_srcoff = (size_t)bk * G4H + bseg * 1024 + hc0 + bnn;

    const uint32_t smb = smem_u32(dsm);

    // gate ids: thread owns 2 elements (gb, ghc), (gb, ghc+1)
    const int li = tid * 2, rb = li >> 5, rc = li & 31;
    const int gb = ks * 32 + rb;
    const int ghc = hc0 + rc;
    float2 creg = make_float2(0.f, 0.f);

    for (int t = 0; t < T_ + L_; ++t) {
        const bool dec = (t >= T_);
        const int st = dec ? t - T_ : t;
        const float* wh = dec ? g_whD : g_whE;
        const float* hsrc = g_hbuf[t % 3];
        const float* xg = (dec ? g_xg_dec : g_xg_enc) + (size_t)st * (B_ * G4H);
        float* zp = g_zp + (size_t)(t & 1) * ZPSZ;

        // preload xg gate inputs (latency hidden under GEMM)
        float2 zx[4];
#pragma unroll
        for (int gt = 0; gt < 4; gt++)
            zx[gt] = *(const float2*)(xg + (size_t)gb * G4H + gt * 1024 + ghc);

        // ---- wait only on the 32 producers of h cols [k0, k0+256) ----
        if (t > 0) {
            if (tid < 32) {
                volatile unsigned* f = &g_flagH[(ks * 32 + tid) * 8];
                while (*f < (unsigned)t) {}
            }
            __threadfence();
            __syncthreads();
        }

        float acc[2][4][4] = {};

        auto issue = [&](int kt32) {
            const uint32_t sb = smb + (uint32_t)((kt32 % 3) * PST_STG) * 4;
            const int kb = k0 + kt32 * 32;
#pragma unroll
            for (int h = 0; h < 2; h++) {
                cpa16(sb + (h * 2048 + a_dst) * 4,
                      hsrc + (size_t)ar * H_ + kb + h * 16 + akq);
                cpa16(sb + (4096 + h * 2048 + b_dst) * 4,
                      wh + (size_t)(kb + h * 16) * G4H + b_srcoff);
            }
        };

        issue(0); CP_COMMIT();
        issue(1); CP_COMMIT();

        const int kA  = (2 * tig) ^ swzA;
        const int kA8 = (2 * tig + 8) ^ swzA;
        const int r0 = 2 * tig, r1 = r0 + 1, r2 = r0 + 8, r3 = r0 + 9;

        for (int kt = 0; kt < PST_NK; ++kt) {
            CP_WAIT1();
            __syncthreads();
            if (kt + 2 < PST_NK) issue(kt + 2);
            CP_COMMIT();

            const float* base = dsm + (kt % 3) * PST_STG;
#pragma unroll
            for (int h = 0; h < 2; h++) {
                const float* a_s = base + h * 2048;
                const float* b_s = base + 4096 + h * 2048;
                uint32_t af[2][4], bf[4][2];
#pragma unroll
                for (int mf = 0; mf < 2; mf++) {
                    const int m0 = wm * 32 + mf * 16 + gid;
                    float2 p;
                    p = *(const float2*)&a_s[m0 * 16 + kA];        af[mf][0] = pack_h2(p.x, p.y);
                    p = *(const float2*)&a_s[(m0 + 8) * 16 + kA];  af[mf][1] = pack_h2(p.x, p.y);
                    p = *(const float2*)&a_s[m0 * 16 + kA8];       af[mf][2] = pack_h2(p.x, p.y);
                    p = *(const float2*)&a_s[(m0 + 8) * 16 + kA8]; af[mf][3] = pack_h2(p.x, p.y);
                }
#pragma unroll
                for (int nf = 0; nf < 4; nf++) {
                    const int n = wn * 32 + nf * 8 + gid;
                    bf[nf][0] = pack_h2(b_s[r0 * 128 + (n ^ ((r0 & 3) << 3))],
                                        b_s[r1 * 128 + (n ^ ((r1 & 3) << 3))]);
                    bf[nf][1] = pack_h2(b_s[r2 * 128 + (n ^ ((r2 & 3) << 3))],
                                        b_s[r3 * 128 + (n ^ ((r3 & 3) << 3))]);
                }
#pragma unroll
                for (int mf = 0; mf < 2; mf++)
#pragma unroll
                    for (int nf = 0; nf < 4; nf++)
                        mma16h(acc[mf][nf], af[mf], bf[nf]);
            }
        }

        // ---- store z partials: zp[bid][row][col] ----
#pragma unroll
        for (int mf = 0; mf < 2; mf++)
#pragma unroll
            for (int nf = 0; nf < 4; nf++) {
                const int col = wn * 32 + nf * 8 + 2 * tig;
                const int mrow = wm * 32 + mf * 16 + gid;
#pragma unroll
                for (int r = 0; r < 2; r++) {
                    const int row = mrow + r * 8;
                    *(float2*)&zp[((size_t)bid * 128 + row) * 128 + col] =
                        make_float2(acc[mf][nf][2 * r], acc[mf][nf][2 * r + 1]);
                }
            }

        // ---- group sync (4 k-split blocks of this n-group) ----
        __syncthreads();
        __threadfence();
        if (tid == 0) *(volatile unsigned*)&g_flagZ[bid * 8] = (unsigned)(t + 1);
        if (tid < 4) {
            volatile unsigned* f = &g_flagZ[(g * 4 + tid) * 8];
            while (*f < (unsigned)(t + 1)) {}
        }
        __threadfence();
        __syncthreads();

        // ---- gates: batch rows [ks*32..+32) x h-cols [hc0..hc0+32) ----
        {
            float2 z[4];
#pragma unroll
            for (int gt = 0; gt < 4; gt++) {
                float2 v = zx[gt];
#pragma unroll
                for (int kp = 0; kp < 4; kp++)
                    v = add2(v, __ldcg((const float2*)(
                        zp + ((size_t)(g * 4 + kp) * 128 + gb) * 128 + gt * 32 + rc)));
                z[gt] = v;
            }
            float2 hn;
            {
                const float ig = sigf(z[0].x);
                const float jg = tanhf(z[1].x);
                const float fg = sigf(z[2].x + 1.0f);   // FORGET_BIAS
                const float og = sigf(z[3].x);
                creg.x = creg.x * fg + ig * jg;
                hn.x = tanhf(creg.x) * og;
            }
            {
                const float ig = sigf(z[0].y);
                const float jg = tanhf(z[1].y);
                const float fg = sigf(z[2].y + 1.0f);
                const float og = sigf(z[3].y);
                creg.y = creg.y * fg + ig * jg;
                hn.y = tanhf(creg.y) * og;
            }
            const float2 ho = make_float2(f2tf(hn.x), f2tf(hn.y));
            *(float2*)(g_hbuf[(t + 1) % 3] + (size_t)gb * H_ + ghc) = ho;
            if (dec)
                *(float2*)(g_hs + ((size_t)st * B_ + gb) * H_ + ghc) = ho;
        }

        // ---- signal gates done ----
        __syncthreads();
        __threadfence();
        if (tid == 0) *(volatile unsigned*)&g_flagH[bid * 8] = (unsigned)(t + 1);
    }
}

// ============================================================================
// mm_tf32 (R8, passing): MODE 1 (dec XG, gather), MODE 2 (projection)
// ============================================================================
#define ASTR 20
#define BSTR 136
struct TIds {
    int lane, wid, wm, wn, gid, tig;
    int ar, ak, bk, bn;
};
__device__ __forceinline__ TIds make_ids(int tid) {
    TIds s;
    s.lane = tid & 31; s.wid = tid >> 5;
    s.wm = s.wid >> 2; s.wn = s.wid & 3;
    s.gid = s.lane >> 2; s.tig = s.lane & 3;
    s.ar = tid >> 2; s.ak = (tid & 3) * 4;
    s.bk = tid >> 5; s.bn = (tid & 31) * 4;
    return s;
}
__device__ __forceinline__ void compute_bk16(
    const float* a_s, const float* b_s, const TIds& s, float acc[2][4][4])
{
#pragma unroll
    for (int ks = 0; ks < 16; ks += 8) {
        float af[2][4], bf[4][2];
#pragma unroll
        for (int mf = 0; mf < 2; mf++) {
            const int m = s.wm * 32 + mf * 16 + s.gid;
            af[mf][0] = a_s[(m)     * ASTR + ks + s.tig];
            af[mf][1] = a_s[(m + 8) * ASTR + ks + s.tig];
            af[mf][2] = a_s[(m)     * ASTR + ks + s.tig + 4];
            af[mf][3] = a_s[(m + 8) * ASTR + ks + s.tig + 4];
        }
#pragma unroll
        for (int nf = 0; nf < 4; nf++) {
            const int n = s.wn * 32 + nf * 8 + s.gid;
            bf[nf][0] = b_s[(ks + s.tig)     * BSTR + n];
            bf[nf][1] = b_s[(ks + s.tig + 4) * BSTR + n];
        }
#pragma unroll
        for (int mf = 0; mf < 2; mf++)
#pragma unroll
            for (int nf = 0; nf < 4; nf++) mma8(acc[mf][nf], af[mf], bf[nf]);
    }
}

template <int MODE>
__global__ void __launch_bounds__(512)
mm_tf32(const float* __restrict__ A, const float* __restrict__ Bm,
        const float* __restrict__ bias, float* __restrict__ Cout,
        const int* __restrict__ caption, int Kv, int ldb)
{
    __shared__ __align__(16) float a_s[2][128 * ASTR];
    __shared__ __align__(16) float b_s[2][16 * BSTR];

    const int tid = threadIdx.x;
    const TIds s = make_ids(tid);
    const int n0 = blockIdx.x * 128;
    const int mtile = blockIdx.y;

    const int m = mtile * 128 + s.ar;
    size_t aoff;
    if constexpr (MODE == 1)
        aoff = (size_t)caption[(m & 127) * L_ + (m >> 7)] * WV_;
    else
        aoff = (size_t)m * H_;
    const float* arow = ((MODE == 2) ? (const float*)g_hs : A) + aoff;

    float acc[2][4][4] = {};
    const int NK = (Kv + 15) / 16;

    auto stage = [&](int it, int buf) {
        const int kb = it * 16;
        {
            const int gk = kb + s.ak;
            float4 v = make_float4(0.f, 0.f, 0.f, 0.f);
            if (MODE != 1 || gk < Kv) v = *(const float4*)(arow + gk);
            *(float4*)&a_s[buf][s.ar * ASTR + s.ak] = tf4(v);
        }
        {
            const int gk = kb + s.bk;
            const int gn = n0 + s.bn;
            float4 v = make_float4(0.f, 0.f, 0.f, 0.f);
            const bool kok = (MODE == 1) ? (gk < Kv) : true;
            const bool nok = (MODE == 2) ? (gn < WV_) : true;
            if (kok && nok) v = *(const float4*)(Bm + (size_t)gk * ldb + gn);
            *(float4*)&b_s[buf][s.bk * BSTR + s.bn] = tf4(v);
        }
    };

    stage(0, 0);
    __syncthreads();
    int buf = 0;
    for (int it = 0; it < NK; ++it) {
        if (it + 1 < NK) stage(it + 1, buf ^ 1);
        compute_bk16(a_s[buf], b_s[buf], s, acc);
        __syncthreads();
        buf ^= 1;
    }

#pragma unroll
    for (int mf = 0; mf < 2; mf++)
#pragma unroll
        for (int nf = 0; nf < 4; nf++) {
            const int col = n0 + s.wn * 32 + nf * 8 + 2 * s.tig;
            const int mrow = mtile * 128 + s.wm * 32 + mf * 16 + s.gid;
#pragma unroll
            for (int r = 0; r < 2; r++) {
                const int row = mrow + r * 8;
                const float v0 = acc[mf][nf][2 * r];
                const float v1 = acc[mf][nf][2 * r + 1];
                if constexpr (MODE == 2) {
                    if (col < WV_) {
                        const size_t co = (size_t)((row & 127) * L_ + (row >> 7)) * WV_;
                        Cout[co + col]     = v0 + bias[col];
                        Cout[co + col + 1] = v1 + bias[col + 1];
                    }
                } else {
                    float* dst = g_xg_dec + (size_t)row * G4H + col;
                    *(float2*)dst = make_float2(v0 + bias[col], v1 + bias[col + 1]);
                }
            }
        }
}

// ---- prep kernels (unchanged) ----
__global__ void __launch_bounds__(512)
conv_wh(const float* __restrict__ encK, const float* __restrict__ decK)
{
    const size_t i4 = ((size_t)blockIdx.x * 512 + threadIdx.x) * 4;
    if (i4 < (size_t)H_ * G4H) {
        *(float4*)&g_whE[i4] = tf4(*(const float4*)(encK + (size_t)F_  * G4H + i4));
        *(float4*)&g_whD[i4] = tf4(*(const float4*)(decK + (size_t)WV_ * G4H + i4));
    }
}

__global__ void __launch_bounds__(512)
conv_wx(const float* __restrict__ encK)
{
    const size_t i4 = ((size_t)blockIdx.x * 512 + threadIdx.x) * 4;
    if (i4 < (size_t)F_ * G4H)
        *(float4*)&g_wx[i4] = tf4(*(const float4*)(encK + i4));
}

__global__ void __launch_bounds__(512)
prep_frames(const float* __restrict__ frames)
{
    const size_t i4 = ((size_t)blockIdx.x * 512 + threadIdx.x) * 4;
    if (i4 < (size_t)4096 * F_) {
        const int m = (int)(i4 / F_), k = (int)(i4 % F_);
        const int b = m & 127, t = m >> 7;
        const float4 v = *(const float4*)(frames + ((size_t)b * T_ + t) * F_ + k);
        *(float4*)&g_frames_tf[i4] = tf4(v);
    }
}

__global__ void init_k()
{
    const int i = blockIdx.x * 256 + threadIdx.x;
    if (i < B_ * H_) g_hbuf[0][i] = 0.f;
    if (i < NBLK * 8) { g_flagZ[i] = 0u; g_flagH[i] = 0u; }
}

// ----------------------------------------------------------------------------
extern "C" void kernel_launch(void* const* d_in, const int* in_sizes, int n_in,
                              void* d_out, int out_size)
{
    const float* frames  = (const float*)d_in[0];
    const int*   caption = (const int*)  d_in[1];
    const float* emb     = (const float*)d_in[2];
    const float* encK    = (const float*)d_in[3];
    const float* encB    = (const float*)d_in[4];
    const float* decK    = (const float*)d_in[5];
    const float* decB    = (const float*)d_in[6];
    const float* projW   = (const float*)d_in[7];
    const float* projB   = (const float*)d_in[8];
    float*       out     = (float*)d_out;

    cudaFuncSetAttribute(mm0_big, cudaFuncAttributeMaxDynamicSharedMemorySize, SMEM_BIG);
    cudaFuncSetAttribute(lstm_persist, cudaFuncAttributeMaxDynamicSharedMemorySize, SMEM_PST);

    init_k<<<512, 256>>>();
    conv_wh<<<2048, 512>>>(encK, decK);
    conv_wx<<<4096, 512>>>(encK);
    prep_frames<<<4096, 512>>>(frames);

    // encoder input gates: [4096,2048] x [2048,4096] + enc_bias (fp16 mma)
    mm0_big<<<dim3(16, 32), 512, SMEM_BIG>>>(encB);

    // decoder input gates: gather(emb) [2560,300] x [300,4096] + dec_bias
    mm_tf32<1><<<dim3(32, 20), 512>>>(emb, decK, decB, nullptr, caption, WV_, G4H);

    // full recurrence (32 enc + 20 dec): relaxed sync + fp16 mma GEMM
    lstm_persist<<<NBLK, 512, SMEM_PST>>>();

    // projection: [2560,1024] x [1024,300] + proj_b -> out[b][l][wv]
    mm_tf32<2><<<dim3(3, 20), 512>>>(nullptr, projW, projB, out, nullptr, H_, WV_);
}

// round 17
// speedup vs baseline: 1.3301x; 1.3301x over previous
#include <cuda_runtime.h>
#include <cuda_fp16.h>
#include <cstdint>

// ----------------------------------------------------------------------------
// B=128, T=32, F=2048, H=1024, L=20, WV=300; TF gate order i,j,f,o; FORGET_BIAS=1
// ----------------------------------------------------------------------------
#define B_   128
#define T_   32
#define F_   2048
#define H_   1024
#define L_   20
#define WV_  300
#define G4H  4096
#define NBLK 128
// persist: 3 stages x (A 128x32 + B 32x128) = 3 x 8192 floats = 96KB
#define PST_STG   8192
#define SMEM_PST  (3 * PST_STG * 4)
#define PST_NK    8          // 8 x BK32 = 256 k per block
#define ZPSZ      ((size_t)128 * 128 * 128)
// mm0 fp16: stage = A 128x32 half (4096) + B 256x32 half (8192) = 12288 halves
#define MM0_AH    4096
#define MM0_STG_H 12288
#define SMEM_MM0  (3 * MM0_STG_H * 2)    // 73728 bytes

// ---------------- device scratch ----------------
__device__ float  g_xg_enc[(size_t)4096 * 4096];   // [t*128+b][4H]
__device__ float  g_xg_dec[(size_t)2560 * 4096];   // [l*128+b][4H]
__device__ float  g_zp[2 * ZPSZ];                  // [t&1][bid][batch 128][col 128]
__device__ float  g_hbuf[3][B_ * H_];              // triple-buffered h (tf32-rounded)
__device__ float  g_hs[(size_t)L_ * B_ * H_];      // decoder outputs
__device__ float  g_whE[(size_t)H_ * G4H];         // tf32-rounded Wh (encoder)
__device__ float  g_whD[(size_t)H_ * G4H];         // tf32-rounded Wh (decoder)
__device__ __half g_frames_h[(size_t)4096 * F_];   // [m=t*128+b][k] half frames
__device__ __half g_wxT_h[(size_t)G4H * F_];       // [n][k] half Wx^T (encoder)
__device__ unsigned g_flagZ[NBLK * 8];             // zp-ready (value = t+1)
__device__ unsigned g_flagH[NBLK * 8];             // gates-done (value = t+1)

// ---------------- helpers ----------------
__device__ __forceinline__ float f2tf(float x) {
    unsigned u;
    asm("cvt.rna.tf32.f32 %0, %1;" : "=r"(u) : "f"(x));
    return __uint_as_float(u);
}
__device__ __forceinline__ float4 tf4(float4 v) {
    return make_float4(f2tf(v.x), f2tf(v.y), f2tf(v.z), f2tf(v.w));
}
__device__ __forceinline__ void mma8(float* c, const float* a, const float* b) {
    asm volatile(
        "mma.sync.aligned.m16n8k8.row.col.f32.tf32.tf32.f32 "
        "{%0,%1,%2,%3},{%4,%5,%6,%7},{%8,%9},{%0,%1,%2,%3};"
        : "+f"(c[0]), "+f"(c[1]), "+f"(c[2]), "+f"(c[3])
        : "r"(__float_as_uint(a[0])), "r"(__float_as_uint(a[1])),
          "r"(__float_as_uint(a[2])), "r"(__float_as_uint(a[3])),
          "r"(__float_as_uint(b[0])), "r"(__float_as_uint(b[1])));
}
__device__ __forceinline__ void mma16h(float* c, const uint32_t* a, const uint32_t* b) {
    asm volatile(
        "mma.sync.aligned.m16n8k16.row.col.f32.f16.f16.f32 "
        "{%0,%1,%2,%3},{%4,%5,%6,%7},{%8,%9},{%0,%1,%2,%3};"
        : "+f"(c[0]), "+f"(c[1]), "+f"(c[2]), "+f"(c[3])
        : "r"(a[0]), "r"(a[1]), "r"(a[2]), "r"(a[3]), "r"(b[0]), "r"(b[1]));
}
__device__ __forceinline__ float2 add2(float2 a, float2 b) {
    a.x += b.x; a.y += b.y; return a;
}
__device__ __forceinline__ float sigf(float x) { return 1.f / (1.f + __expf(-x)); }

__device__ __forceinline__ uint32_t smem_u32(const void* p) {
    return (uint32_t)__cvta_generic_to_shared(p);
}
__device__ __forceinline__ void cpa16(uint32_t dst, const void* src) {
    asm volatile("cp.async.cg.shared.global [%0], [%1], 16;" :: "r"(dst), "l"(src));
}
#define CP_COMMIT() asm volatile("cp.async.commit_group;")
#define CP_WAIT1()  asm volatile("cp.async.wait_group 1;")

// half offset of element (row, hc) in a 32-half-wide tile with 16B-unit XOR swizzle
__device__ __forceinline__ int hoff(int row, int hc) {
    return row * 32 + ((((hc >> 3) ^ (row & 3))) << 3) + (hc & 7);
}

// ============================================================================
// mm0_h: enc XG GEMM, tile 128m x 256n, BK=32, native-half smem, fp16 mma.
// A = g_frames_h[m][k]; B = g_wxT_h[n][k] (both K-major, fragments contiguous).
// Fragment map identical to R16-validated one (rebased onto half storage).
// ============================================================================
__global__ void __launch_bounds__(512)
mm0_h(const float* __restrict__ bias)
{
    extern __shared__ __half hsm[];
    const int tid = threadIdx.x;
    const int lane = tid & 31, wid = tid >> 5;
    const int wm = wid >> 2, wn = wid & 3;
    const int gid = lane >> 2, tig = lane & 3;
    const int ntile = blockIdx.x, mtile = blockIdx.y;

    // staging ids: row = tid>>2 (0..127), unit = tid&3 (16B k-chunk)
    const int srow = tid >> 2, sunit = tid & 3;
    const int a_dst = hoff(srow, sunit * 8);            // A row srow
    const uint32_t smb = smem_u32(hsm);

    const __half* asrc = g_frames_h + (size_t)(mtile * 128 + srow) * F_ + sunit * 8;
    const __half* bsrc0 = g_wxT_h + (size_t)(ntile * 256 + srow) * F_ + sunit * 8;
    const __half* bsrc1 = bsrc0 + (size_t)128 * F_;
    const int b_dst0 = MM0_AH + hoff(srow, sunit * 8);
    const int b_dst1 = MM0_AH + hoff(srow + 128, sunit * 8);  // (row+128)&3 == row&3

    float acc[2][8][4] = {};
    const int NK = F_ / 32;    // 64 stages

    auto issue = [&](int st) {
        const uint32_t sb = smb + (uint32_t)((st % 3) * MM0_STG_H) * 2;
        const int kb = st * 32;
        cpa16(sb + a_dst * 2, asrc + kb);
        cpa16(sb + b_dst0 * 2, bsrc0 + kb);
        cpa16(sb + b_dst1 * 2, bsrc1 + kb);
    };

    issue(0); CP_COMMIT();
    issue(1); CP_COMMIT();

    for (int kt = 0; kt < NK; ++kt) {
        CP_WAIT1();
        __syncthreads();
        if (kt + 2 < NK) issue(kt + 2);
        CP_COMMIT();

        const __half* a_s = hsm + (kt % 3) * MM0_STG_H;
        const __half* b_s = a_s + MM0_AH;
#pragma unroll
        for (int kk = 0; kk < 32; kk += 16) {
            uint32_t af[2][4], bf[8][2];
            const int h0 = kk + 2 * tig, h1 = kk + 2 * tig + 8;
#pragma unroll
            for (int mf = 0; mf < 2; mf++) {
                const int m0 = wm * 32 + mf * 16 + gid;
                af[mf][0] = *(const uint32_t*)&a_s[hoff(m0,     h0)];
                af[mf][1] = *(const uint32_t*)&a_s[hoff(m0 + 8, h0)];
                af[mf][2] = *(const uint32_t*)&a_s[hoff(m0,     h1)];
                af[mf][3] = *(const uint32_t*)&a_s[hoff(m0 + 8, h1)];
            }
#pragma unroll
            for (int nf = 0; nf < 8; nf++) {
                const int n = wn * 64 + nf * 8 + gid;
                bf[nf][0] = *(const uint32_t*)&b_s[hoff(n, h0)];
                bf[nf][1] = *(const uint32_t*)&b_s[hoff(n, h1)];
            }
#pragma unroll
            for (int mf = 0; mf < 2; mf++)
#pragma unroll
                for (int nf = 0; nf < 8; nf++) mma16h(acc[mf][nf], af[mf], bf[nf]);
        }
    }

    // epilogue (layout identical to validated R16 mm0)
#pragma unroll
    for (int mf = 0; mf < 2; mf++)
#pragma unroll
        for (int nf = 0; nf < 8; nf++) {
            const int col = ntile * 256 + wn * 64 + nf * 8 + 2 * tig;
            const float2 bb = *(const float2*)(bias + col);
#pragma unroll
            for (int r = 0; r < 2; r++) {
                const int row = mtile * 128 + wm * 32 + mf * 16 + gid + r * 8;
                *(float2*)&g_xg_enc[(size_t)row * G4H + col] =
                    make_float2(acc[mf][nf][2 * r] + bb.x,
                                acc[mf][nf][2 * r + 1] + bb.y);
            }
        }
}

// ============================================================================
// Persistent recurrence — byte-identical to R15 (passing, 1456us).
// ============================================================================
__global__ void __launch_bounds__(512)
lstm_persist()
{
    extern __shared__ float dsm[];
    const int tid = threadIdx.x, bid = blockIdx.x;
    const int g = bid >> 2, ks = bid & 3;
    const int hc0 = g * 32;
    const int k0 = ks * 256;

    const int lane = tid & 31, wid = tid >> 5;
    const int wm = wid >> 2, wn = wid & 3;
    const int gid = lane >> 2, tig = lane & 3;
    const int swzA = ((gid >> 1) & 3) << 2;
    const int swzB = tig * 8;

    const int ar = tid >> 2, akq = (tid & 3) * 4;
    const int a_dst = ar * 16 + (akq ^ (((ar >> 1) & 3) << 2));
    const int bk = tid >> 5, bseg = (tid & 31) >> 3, bnn = (tid & 7) * 4;
    const int b_dst = bk * 128 + ((bseg * 32 + bnn) ^ ((bk & 3) * 8));
    const size_t b_srcoff = (size_t)bk * G4H + bseg * 1024 + hc0 + bnn;

    const uint32_t smb = smem_u32(dsm);

    const int li = tid * 2, rb = li >> 5, rc = li & 31;
    const int gb = ks * 32 + rb;
    const int ghc = hc0 + rc;
    float2 creg = make_float2(0.f, 0.f);

    for (int t = 0; t < T_ + L_; ++t) {
        const bool dec = (t >= T_);
        const int st = dec ? t - T_ : t;
        const float* wh = dec ? g_whD : g_whE;
        const float* hsrc = g_hbuf[t % 3];
        const float* xg = (dec ? g_xg_dec : g_xg_enc) + (size_t)st * (B_ * G4H);
        float* zp = g_zp + (size_t)(t & 1) * ZPSZ;

        float2 zx[4];
#pragma unroll
        for (int gt = 0; gt < 4; gt++)
            zx[gt] = *(const float2*)(xg + (size_t)gb * G4H + gt * 1024 + ghc);

        if (t > 0) {
            if (tid < 32) {
                volatile unsigned* f = &g_flagH[(ks * 32 + tid) * 8];
                while (*f < (unsigned)t) {}
            }
            __threadfence();
            __syncthreads();
        }

        float acc[2][4][4] = {};

        auto issue = [&](int kt32) {
            const uint32_t sb = smb + (uint32_t)((kt32 % 3) * PST_STG) * 4;
            const int kb = k0 + kt32 * 32;
#pragma unroll
            for (int h = 0; h < 2; h++) {
                cpa16(sb + (h * 2048 + a_dst) * 4,
                      hsrc + (size_t)ar * H_ + kb + h * 16 + akq);
                cpa16(sb + (4096 + h * 2048 + b_dst) * 4,
                      wh + (size_t)(kb + h * 16) * G4H + b_srcoff);
            }
        };

        issue(0); CP_COMMIT();
        issue(1); CP_COMMIT();

        for (int kt = 0; kt < PST_NK; ++kt) {
            CP_WAIT1();
            __syncthreads();
            if (kt + 2 < PST_NK) issue(kt + 2);
            CP_COMMIT();

            const float* base = dsm + (kt % 3) * PST_STG;
#pragma unroll
            for (int h = 0; h < 2; h++) {
                const float* a_s = base + h * 2048;
                const float* b_s = base + 4096 + h * 2048;
#pragma unroll
                for (int kss = 0; kss < 16; kss += 8) {
                    float af[2][4], bf[4][2];
#pragma unroll
                    for (int mf = 0; mf < 2; mf++) {
                        const int m0 = wm * 32 + mf * 16 + gid;
                        const int c0 = (kss + tig) ^ swzA;
                        const int c1 = (kss + tig + 4) ^ swzA;
                        af[mf][0] = a_s[m0 * 16 + c0];
                        af[mf][1] = a_s[(m0 + 8) * 16 + c0];
                        af[mf][2] = a_s[m0 * 16 + c1];
                        af[mf][3] = a_s[(m0 + 8) * 16 + c1];
                    }
#pragma unroll
                    for (int nf = 0; nf < 4; nf++) {
                        const int n = wn * 32 + nf * 8 + gid;
                        bf[nf][0] = b_s[(kss + tig) * 128 + (n ^ swzB)];
                        bf[nf][1] = b_s[(kss + tig + 4) * 128 + (n ^ swzB)];
                    }
#pragma unroll
                    for (int mf = 0; mf < 2; mf++)
#pragma unroll
                        for (int nf = 0; nf < 4; nf++)
                            mma8(acc[mf][nf], af[mf], bf[nf]);
                }
            }
        }

#pragma unroll
        for (int mf = 0; mf < 2; mf++)
#pragma unroll
            for (int nf = 0; nf < 4; nf++) {
                const int col = wn * 32 + nf * 8 + 2 * tig;
                const int mrow = wm * 32 + mf * 16 + gid;
#pragma unroll
                for (int r = 0; r < 2; r++) {
                    const int row = mrow + r * 8;
                    *(float2*)&zp[((size_t)bid * 128 + row) * 128 + col] =
                        make_float2(acc[mf][nf][2 * r], acc[mf][nf][2 * r + 1]);
                }
            }

        __syncthreads();
        __threadfence();
        if (tid == 0) *(volatile unsigned*)&g_flagZ[bid * 8] = (unsigned)(t + 1);
        if (tid < 4) {
            volatile unsigned* f = &g_flagZ[(g * 4 + tid) * 8];
            while (*f < (unsigned)(t + 1)) {}
        }
        __threadfence();
        __syncthreads();

        {
            float2 z[4];
#pragma unroll
            for (int gt = 0; gt < 4; gt++) {
                float2 v = zx[gt];
#pragma unroll
                for (int kp = 0; kp < 4; kp++)
                    v = add2(v, __ldcg((const float2*)(
                        zp + ((size_t)(g * 4 + kp) * 128 + gb) * 128 + gt * 32 + rc)));
                z[gt] = v;
            }
            float2 hn;
            {
                const float ig = sigf(z[0].x);
                const float jg = tanhf(z[1].x);
                const float fg = sigf(z[2].x + 1.0f);   // FORGET_BIAS
                const float og = sigf(z[3].x);
                creg.x = creg.x * fg + ig * jg;
                hn.x = tanhf(creg.x) * og;
            }
            {
                const float ig = sigf(z[0].y);
                const float jg = tanhf(z[1].y);
                const float fg = sigf(z[2].y + 1.0f);
                const float og = sigf(z[3].y);
                creg.y = creg.y * fg + ig * jg;
                hn.y = tanhf(creg.y) * og;
            }
            const float2 ho = make_float2(f2tf(hn.x), f2tf(hn.y));
            *(float2*)(g_hbuf[(t + 1) % 3] + (size_t)gb * H_ + ghc) = ho;
            if (dec)
                *(float2*)(g_hs + ((size_t)st * B_ + gb) * H_ + ghc) = ho;
        }

        __syncthreads();
        __threadfence();
        if (tid == 0) *(volatile unsigned*)&g_flagH[bid * 8] = (unsigned)(t + 1);
    }
}

// ============================================================================
// mm_tf32 (R8, passing): MODE 1 (dec XG, gather), MODE 2 (projection)
// ============================================================================
#define ASTR 20
#define BSTR 136
struct TIds {
    int lane, wid, wm, wn, gid, tig;
    int ar, ak, bk, bn;
};
__device__ __forceinline__ TIds make_ids(int tid) {
    TIds s;
    s.lane = tid & 31; s.wid = tid >> 5;
    s.wm = s.wid >> 2; s.wn = s.wid & 3;
    s.gid = s.lane >> 2; s.tig = s.lane & 3;
    s.ar = tid >> 2; s.ak = (tid & 3) * 4;
    s.bk = tid >> 5; s.bn = (tid & 31) * 4;
    return s;
}
__device__ __forceinline__ void compute_bk16(
    const float* a_s, const float* b_s, const TIds& s, float acc[2][4][4])
{
#pragma unroll
    for (int ks = 0; ks < 16; ks += 8) {
        float af[2][4], bf[4][2];
#pragma unroll
        for (int mf = 0; mf < 2; mf++) {
            const int m = s.wm * 32 + mf * 16 + s.gid;
            af[mf][0] = a_s[(m)     * ASTR + ks + s.tig];
            af[mf][1] = a_s[(m + 8) * ASTR + ks + s.tig];
            af[mf][2] = a_s[(m)     * ASTR + ks + s.tig + 4];
            af[mf][3] = a_s[(m + 8) * ASTR + ks + s.tig + 4];
        }
#pragma unroll
        for (int nf = 0; nf < 4; nf++) {
            const int n = s.wn * 32 + nf * 8 + s.gid;
            bf[nf][0] = b_s[(ks + s.tig)     * BSTR + n];
            bf[nf][1] = b_s[(ks + s.tig + 4) * BSTR + n];
        }
#pragma unroll
        for (int mf = 0; mf < 2; mf++)
#pragma unroll
            for (int nf = 0; nf < 4; nf++) mma8(acc[mf][nf], af[mf], bf[nf]);
    }
}

template <int MODE>
__global__ void __launch_bounds__(512)
mm_tf32(const float* __restrict__ A, const float* __restrict__ Bm,
        const float* __restrict__ bias, float* __restrict__ Cout,
        const int* __restrict__ caption, int Kv, int ldb)
{
    __shared__ __align__(16) float a_s[2][128 * ASTR];
    __shared__ __align__(16) float b_s[2][16 * BSTR];

    const int tid = threadIdx.x;
    const TIds s = make_ids(tid);
    const int n0 = blockIdx.x * 128;
    const int mtile = blockIdx.y;

    const int m = mtile * 128 + s.ar;
    size_t aoff;
    if constexpr (MODE == 1)
        aoff = (size_t)caption[(m & 127) * L_ + (m >> 7)] * WV_;
    else
        aoff = (size_t)m * H_;
    const float* arow = ((MODE == 2) ? (const float*)g_hs : A) + aoff;

    float acc[2][4][4] = {};
    const int NK = (Kv + 15) / 16;

    auto stage = [&](int it, int buf) {
        const int kb = it * 16;
        {
            const int gk = kb + s.ak;
            float4 v = make_float4(0.f, 0.f, 0.f, 0.f);
            if (MODE != 1 || gk < Kv) v = *(const float4*)(arow + gk);
            *(float4*)&a_s[buf][s.ar * ASTR + s.ak] = tf4(v);
        }
        {
            const int gk = kb + s.bk;
            const int gn = n0 + s.bn;
            float4 v = make_float4(0.f, 0.f, 0.f, 0.f);
            const bool kok = (MODE == 1) ? (gk < Kv) : true;
            const bool nok = (MODE == 2) ? (gn < WV_) : true;
            if (kok && nok) v = *(const float4*)(Bm + (size_t)gk * ldb + gn);
            *(float4*)&b_s[buf][s.bk * BSTR + s.bn] = tf4(v);
        }
    };

    stage(0, 0);
    __syncthreads();
    int buf = 0;
    for (int it = 0; it < NK; ++it) {
        if (it + 1 < NK) stage(it + 1, buf ^ 1);
        compute_bk16(a_s[buf], b_s[buf], s, acc);
        __syncthreads();
        buf ^= 1;
    }

#pragma unroll
    for (int mf = 0; mf < 2; mf++)
#pragma unroll
        for (int nf = 0; nf < 4; nf++) {
            const int col = n0 + s.wn * 32 + nf * 8 + 2 * s.tig;
            const int mrow = mtile * 128 + s.wm * 32 + mf * 16 + s.gid;
#pragma unroll
            for (int r = 0; r < 2; r++) {
                const int row = mrow + r * 8;
                const float v0 = acc[mf][nf][2 * r];
                const float v1 = acc[mf][nf][2 * r + 1];
                if constexpr (MODE == 2) {
                    if (col < WV_) {
                        const size_t co = (size_t)((row & 127) * L_ + (row >> 7)) * WV_;
                        Cout[co + col]     = v0 + bias[col];
                        Cout[co + col + 1] = v1 + bias[col + 1];
                    }
                } else {
                    float* dst = g_xg_dec + (size_t)row * G4H + col;
                    *(float2*)dst = make_float2(v0 + bias[col], v1 + bias[col + 1]);
                }
            }
        }
}

// ---- prep kernels ----
__global__ void __launch_bounds__(512)
conv_wh(const float* __restrict__ encK, const float* __restrict__ decK)
{
    const size_t i4 = ((size_t)blockIdx.x * 512 + threadIdx.x) * 4;
    if (i4 < (size_t)H_ * G4H) {
        *(float4*)&g_whE[i4] = tf4(*(const float4*)(encK + (size_t)F_  * G4H + i4));
        *(float4*)&g_whD[i4] = tf4(*(const float4*)(decK + (size_t)WV_ * G4H + i4));
    }
}

__global__ void __launch_bounds__(512)
prep_frames_h(const float* __restrict__ frames)
{
    const size_t i4 = ((size_t)blockIdx.x * 512 + threadIdx.x) * 4;
    if (i4 < (size_t)4096 * F_) {
        const int m = (int)(i4 / F_), k = (int)(i4 % F_);
        const int b = m & 127, t = m >> 7;
        const float4 v = *(const float4*)(frames + ((size_t)b * T_ + t) * F_ + k);
        __half2 h0 = __floats2half2_rn(v.x, v.y);
        __half2 h1 = __floats2half2_rn(v.z, v.w);
        *(__half2*)&g_frames_h[i4] = h0;
        *(__half2*)&g_frames_h[i4 + 2] = h1;
    }
}

// transpose encK[k][n] (k<F_) -> g_wxT_h[n][k] half
__global__ void __launch_bounds__(256)
prep_wxT(const float* __restrict__ encK)
{
    __shared__ float tile[32][33];
    const int kx = blockIdx.x * 32;
    const int nx = blockIdx.y * 32;
    const int tx = threadIdx.x & 31, ty = threadIdx.x >> 5;
#pragma unroll
    for (int i = ty; i < 32; i += 8)
        tile[i][tx] = encK[(size_t)(kx + i) * G4H + nx + tx];
    __syncthreads();
#pragma unroll
    for (int i = ty; i < 32; i += 8)
        g_wxT_h[(size_t)(nx + i) * F_ + kx + tx] = __float2half_rn(tile[tx][i]);
}

__global__ void init_k()
{
    const int i = blockIdx.x * 256 + threadIdx.x;
    if (i < B_ * H_) g_hbuf[0][i] = 0.f;
    if (i < NBLK * 8) { g_flagZ[i] = 0u; g_flagH[i] = 0u; }
}

// ----------------------------------------------------------------------------
extern "C" void kernel_launch(void* const* d_in, const int* in_sizes, int n_in,
                              void* d_out, int out_size)
{
    const float* frames  = (const float*)d_in[0];
    const int*   caption = (const int*)  d_in[1];
    const float* emb     = (const float*)d_in[2];
    const float* encK    = (const float*)d_in[3];
    const float* encB    = (const float*)d_in[4];
    const float* decK    = (const float*)d_in[5];
    const float* decB    = (const float*)d_in[6];
    const float* projW   = (const float*)d_in[7];
    const float* projB   = (const float*)d_in[8];
    float*       out     = (float*)d_out;

    cudaFuncSetAttribute(mm0_h, cudaFuncAttributeMaxDynamicSharedMemorySize, SMEM_MM0);
    cudaFuncSetAttribute(lstm_persist, cudaFuncAttributeMaxDynamicSharedMemorySize, SMEM_PST);

    init_k<<<512, 256>>>();
    conv_wh<<<2048, 512>>>(encK, decK);
    prep_frames_h<<<4096, 512>>>(frames);
    prep_wxT<<<dim3(64, 128), 256>>>(encK);

    // encoder input gates: [4096,2048] x [2048,4096] + enc_bias (native-fp16 mma)
    mm0_h<<<dim3(16, 32), 512, SMEM_MM0>>>(encB);

    // decoder input gates: gather(emb) [2560,300] x [300,4096] + dec_bias
    mm_tf32<1><<<dim3(32, 20), 512>>>(emb, decK, decB, nullptr, caption, WV_, G4H);

    // full recurrence (32 enc + 20 dec): R15 persistent kernel (tf32, verified)
    lstm_persist<<<NBLK, 512, SMEM_PST>>>();

    // projection: [2560,1024] x [1024,300] + proj_b -> out[b][l][wv]
    mm_tf32<2><<<dim3(3, 20), 512>>>(nullptr, projW, projB, out, nullptr, H_, WV_);
}